// round 2
// baseline (speedup 1.0000x reference)
#include <cuda_runtime.h>
#include <cstdint>

// Problem constants (from reference setup_inputs)
#define NJ 52          // joints
#define NB 32          // batches
#define BSPLIT 2       // batch groups across gridDim.y
#define B_PER (NB / BSPLIT)   // 16 batches per CTA
#define TILE_V 256     // vertices per CTA == blockDim.x

// d = a*b + d, packed 2x fp32 (SASS FFMA2)
__device__ __forceinline__ void fma2(unsigned long long& d,
                                     unsigned long long a,
                                     unsigned long long b) {
    asm("fma.rn.f32x2 %0, %1, %2, %0;" : "+l"(d) : "l"(a), "l"(b));
}

__device__ __forceinline__ unsigned long long pack2(float w) {
    unsigned long long r;
    asm("mov.b64 %0, {%1, %1};" : "=l"(r) : "f"(w));
    return r;
}

__device__ __forceinline__ void unpack2(unsigned long long a, float& lo, float& hi) {
    asm("mov.b64 {%0, %1}, %2;" : "=f"(lo), "=f"(hi) : "l"(a));
}

__device__ __forceinline__ unsigned long long d2ll(double d) {
    return __double_as_longlong(d);
}

__global__ __launch_bounds__(TILE_V)
void skinning_kernel(const float* __restrict__ verts,   // [V,3]
                     const float* __restrict__ W,       // [V,NJ]
                     const float* __restrict__ M,       // [NB,NJ,4,4]
                     float* __restrict__ out,           // [NB,V,3]
                     int V) {
    // Stage rows 0..2 of each 4x4 transform for B_PER batches: [B_PER][NJ][12] floats.
    // 16B alignment is REQUIRED: we read this as double2 (LDS.128).
    __shared__ __align__(16) float Ms[B_PER * NJ * 12];   // 39936 B

    const int tid = threadIdx.x;
    const int b0 = blockIdx.y * B_PER;

    for (int idx = tid; idx < B_PER * NJ * 12; idx += TILE_V) {
        int bj = idx / 12;      // local b*NJ + j
        int k  = idx % 12;      // element within rows 0..2
        Ms[idx] = M[((size_t)(b0) * NJ + bj) * 16 + k];
    }
    __syncthreads();

    const int v = blockIdx.x * TILE_V + tid;
    if (v >= V) return;

    // Per-vertex weights into registers (row is 208 B, 16B-aligned, 13 x float4)
    float w[NJ];
    {
        const float4* wp = reinterpret_cast<const float4*>(W + (size_t)v * NJ);
        #pragma unroll
        for (int q = 0; q < NJ / 4; q++) {
            float4 t = wp[q];
            w[4 * q + 0] = t.x;
            w[4 * q + 1] = t.y;
            w[4 * q + 2] = t.z;
            w[4 * q + 3] = t.w;
        }
    }

    const float x = verts[(size_t)v * 3 + 0];
    const float y = verts[(size_t)v * 3 + 1];
    const float z = verts[(size_t)v * 3 + 2];

    // Each (b,j) entry = 12 floats = 3 x double2 (16B each), 16B-aligned.
    const double2* msd = reinterpret_cast<const double2*>(Ms);

    for (int bb = 0; bb < B_PER; ++bb) {
        unsigned long long a0 = 0, a1 = 0, a2 = 0, a3 = 0, a4 = 0, a5 = 0;
        const double2* mp = msd + (size_t)bb * NJ * 3;

        #pragma unroll
        for (int j = 0; j < NJ; ++j) {
            unsigned long long ww = pack2(w[j]);
            double2 p0 = mp[3 * j + 0];   // {T00,T01},{T02,T03}
            double2 p1 = mp[3 * j + 1];   // {T10,T11},{T12,T13}
            double2 p2 = mp[3 * j + 2];   // {T20,T21},{T22,T23}
            fma2(a0, ww, d2ll(p0.x));
            fma2(a1, ww, d2ll(p0.y));
            fma2(a2, ww, d2ll(p1.x));
            fma2(a3, ww, d2ll(p1.y));
            fma2(a4, ww, d2ll(p2.x));
            fma2(a5, ww, d2ll(p2.y));
        }

        float t00, t01, t02, t03, t10, t11, t12, t13, t20, t21, t22, t23;
        unpack2(a0, t00, t01);
        unpack2(a1, t02, t03);
        unpack2(a2, t10, t11);
        unpack2(a3, t12, t13);
        unpack2(a4, t20, t21);
        unpack2(a5, t22, t23);

        float o0 = fmaf(t00, x, fmaf(t01, y, fmaf(t02, z, t03)));
        float o1 = fmaf(t10, x, fmaf(t11, y, fmaf(t12, z, t13)));
        float o2 = fmaf(t20, x, fmaf(t21, y, fmaf(t22, z, t23)));

        float* op = out + ((size_t)(b0 + bb) * V + v) * 3;
        op[0] = o0;
        op[1] = o1;
        op[2] = o2;
    }
}

extern "C" void kernel_launch(void* const* d_in, const int* in_sizes, int n_in,
                              void* d_out, int out_size) {
    const float* verts = (const float*)d_in[0];   // [1,V,3]
    const float* W     = (const float*)d_in[1];   // [1,V,NJ]
    const float* M     = (const float*)d_in[2];   // [NB,NJ,4,4]
    float* out         = (float*)d_out;           // [NB,V,3]

    const int V = in_sizes[0] / 3;

    dim3 grid((V + TILE_V - 1) / TILE_V, BSPLIT);
    skinning_kernel<<<grid, TILE_V>>>(verts, W, M, out, V);
}

// round 4
// speedup vs baseline: 1.4271x; 1.4271x over previous
#include <cuda_runtime.h>
#include <cstdint>

// Problem constants (from reference setup_inputs)
#define NJ 52          // joints
#define NB 32          // batches
#define BSPLIT 2       // batch groups across gridDim.y
#define B_PER (NB / BSPLIT)   // 16 batches per CTA
#define THREADS 128    // threads per CTA
#define VPT 2          // vertices per thread
#define VPC (THREADS * VPT)   // 256 vertices per CTA

// d = a*b + d, packed 2x fp32 (SASS FFMA2)
__device__ __forceinline__ void fma2(unsigned long long& d,
                                     unsigned long long a,
                                     unsigned long long b) {
    asm("fma.rn.f32x2 %0, %1, %2, %0;" : "+l"(d) : "l"(a), "l"(b));
}

__device__ __forceinline__ unsigned long long pack2(float w) {
    unsigned long long r;
    asm("mov.b64 %0, {%1, %1};" : "=l"(r) : "f"(w));
    return r;
}

__device__ __forceinline__ void unpack2(unsigned long long a, float& lo, float& hi) {
    asm("mov.b64 {%0, %1}, %2;" : "=f"(lo), "=f"(hi) : "l"(a));
}

__device__ __forceinline__ unsigned long long d2ll(double d) {
    return __double_as_longlong(d);
}

__global__ __launch_bounds__(THREADS, 3)
void skinning_kernel(const float* __restrict__ verts,   // [V,3]
                     const float* __restrict__ W,       // [V,NJ]
                     const float* __restrict__ M,       // [NB,NJ,4,4]
                     float* __restrict__ out,           // [NB,V,3]
                     int V) {
    // Rows 0..2 of each 4x4 transform for B_PER batches: [B_PER][NJ][12] floats.
    // 16B alignment REQUIRED: read as double2 (LDS.128).
    __shared__ __align__(16) float Ms[B_PER * NJ * 12];   // 39936 B

    const int tid = threadIdx.x;
    const int b0 = blockIdx.y * B_PER;

    for (int idx = tid; idx < B_PER * NJ * 12; idx += THREADS) {
        int bj = idx / 12;
        int k  = idx % 12;
        Ms[idx] = M[((size_t)b0 * NJ + bj) * 16 + k];
    }
    __syncthreads();

    // Two vertices per thread; consecutive lanes -> consecutive v (coalesced).
    const int v0 = blockIdx.x * VPC + tid;          // always < V for this grid
    const int v1 = v0 + THREADS;                    // may exceed V on last CTA
    const bool has1 = (v1 < V);
    const int v1c = has1 ? v1 : (V - 1);            // clamp loads, guard stores

    // Weight rows, pre-packed as {w,w} u64 pairs (reused across all 16 batches).
    unsigned long long pwA[NJ], pwB[NJ];
    {
        const float4* wp0 = reinterpret_cast<const float4*>(W + (size_t)v0 * NJ);
        const float4* wp1 = reinterpret_cast<const float4*>(W + (size_t)v1c * NJ);
        #pragma unroll
        for (int q = 0; q < NJ / 4; q++) {
            float4 t0 = wp0[q];
            pwA[4 * q + 0] = pack2(t0.x); pwA[4 * q + 1] = pack2(t0.y);
            pwA[4 * q + 2] = pack2(t0.z); pwA[4 * q + 3] = pack2(t0.w);
            float4 t1 = wp1[q];
            pwB[4 * q + 0] = pack2(t1.x); pwB[4 * q + 1] = pack2(t1.y);
            pwB[4 * q + 2] = pack2(t1.z); pwB[4 * q + 3] = pack2(t1.w);
        }
    }

    const float xA = verts[(size_t)v0 * 3 + 0];
    const float yA = verts[(size_t)v0 * 3 + 1];
    const float zA = verts[(size_t)v0 * 3 + 2];
    const float xB = verts[(size_t)v1c * 3 + 0];
    const float yB = verts[(size_t)v1c * 3 + 1];
    const float zB = verts[(size_t)v1c * 3 + 2];

    const double2* msd = reinterpret_cast<const double2*>(Ms);

    for (int bb = 0; bb < B_PER; ++bb) {
        unsigned long long a0 = 0, a1 = 0, a2 = 0, a3 = 0, a4 = 0, a5 = 0;
        unsigned long long c0 = 0, c1 = 0, c2 = 0, c3 = 0, c4 = 0, c5 = 0;
        const double2* mp = msd + (size_t)bb * NJ * 3;

        #pragma unroll
        for (int j = 0; j < NJ; ++j) {
            unsigned long long wwA = pwA[j];
            unsigned long long wwB = pwB[j];
            double2 p0 = mp[3 * j + 0];   // {T00,T01},{T02,T03}
            double2 p1 = mp[3 * j + 1];   // {T10,T11},{T12,T13}
            double2 p2 = mp[3 * j + 2];   // {T20,T21},{T22,T23}
            fma2(a0, wwA, d2ll(p0.x));
            fma2(c0, wwB, d2ll(p0.x));
            fma2(a1, wwA, d2ll(p0.y));
            fma2(c1, wwB, d2ll(p0.y));
            fma2(a2, wwA, d2ll(p1.x));
            fma2(c2, wwB, d2ll(p1.x));
            fma2(a3, wwA, d2ll(p1.y));
            fma2(c3, wwB, d2ll(p1.y));
            fma2(a4, wwA, d2ll(p2.x));
            fma2(c4, wwB, d2ll(p2.x));
            fma2(a5, wwA, d2ll(p2.y));
            fma2(c5, wwB, d2ll(p2.y));
        }

        // Epilogue vertex A
        {
            float t00, t01, t02, t03, t10, t11, t12, t13, t20, t21, t22, t23;
            unpack2(a0, t00, t01); unpack2(a1, t02, t03);
            unpack2(a2, t10, t11); unpack2(a3, t12, t13);
            unpack2(a4, t20, t21); unpack2(a5, t22, t23);
            float o0 = fmaf(t00, xA, fmaf(t01, yA, fmaf(t02, zA, t03)));
            float o1 = fmaf(t10, xA, fmaf(t11, yA, fmaf(t12, zA, t13)));
            float o2 = fmaf(t20, xA, fmaf(t21, yA, fmaf(t22, zA, t23)));
            float* op = out + ((size_t)(b0 + bb) * V + v0) * 3;
            op[0] = o0; op[1] = o1; op[2] = o2;
        }
        // Epilogue vertex B
        if (has1) {
            float t00, t01, t02, t03, t10, t11, t12, t13, t20, t21, t22, t23;
            unpack2(c0, t00, t01); unpack2(c1, t02, t03);
            unpack2(c2, t10, t11); unpack2(c3, t12, t13);
            unpack2(c4, t20, t21); unpack2(c5, t22, t23);
            float o0 = fmaf(t00, xB, fmaf(t01, yB, fmaf(t02, zB, t03)));
            float o1 = fmaf(t10, xB, fmaf(t11, yB, fmaf(t12, zB, t13)));
            float o2 = fmaf(t20, xB, fmaf(t21, yB, fmaf(t22, zB, t23)));
            float* op = out + ((size_t)(b0 + bb) * V + v1) * 3;
            op[0] = o0; op[1] = o1; op[2] = o2;
        }
    }
}

extern "C" void kernel_launch(void* const* d_in, const int* in_sizes, int n_in,
                              void* d_out, int out_size) {
    const float* verts = (const float*)d_in[0];   // [1,V,3]
    const float* W     = (const float*)d_in[1];   // [1,V,NJ]
    const float* M     = (const float*)d_in[2];   // [NB,NJ,4,4]
    float* out         = (float*)d_out;           // [NB,V,3]

    const int V = in_sizes[0] / 3;

    dim3 grid((V + VPC - 1) / VPC, BSPLIT);
    skinning_kernel<<<grid, THREADS>>>(verts, W, M, out, V);
}